// round 4
// baseline (speedup 1.0000x reference)
#include <cuda_runtime.h>
#include <cuda_bf16.h>

#define N_NODES_MAX 1000000
#define KE_HALF 7.199822675975274f   // 14.399645351950548 / 2

// Per-node precomputed table: .x = z (float), .y = z^p * d
__device__ float2 g_node[N_NODES_MAX];
// a0..a3, c0..c3 (c normalized)
__device__ float g_params[8];

__device__ __forceinline__ float softplus_f(float x) {
    return log1pf(expf(x));
}

__global__ void prep_kernel(const int* __restrict__ species,
                            const int* __restrict__ index_to_z,
                            const float* __restrict__ a_raw,
                            const float* __restrict__ c_raw,
                            const float* __restrict__ p_raw,
                            const float* __restrict__ d_raw,
                            float* __restrict__ out,
                            int n_nodes) {
    int i = blockIdx.x * blockDim.x + threadIdx.x;

    if (i < 8) {
        if (i < 4) {
            g_params[i] = softplus_f(a_raw[i]);
        } else {
            float c0 = softplus_f(c_raw[0]);
            float c1 = softplus_f(c_raw[1]);
            float c2 = softplus_f(c_raw[2]);
            float c3 = softplus_f(c_raw[3]);
            float inv_s = 1.0f / (c0 + c1 + c2 + c3);
            g_params[i] = softplus_f(c_raw[i - 4]) * inv_s;
        }
    }

    if (i < n_nodes) {
        out[i] = 0.0f;  // zero-init accumulator (harness poisons d_out)
        float p = softplus_f(p_raw[0]);
        float d = softplus_f(d_raw[0]);
        float z = (float)index_to_z[species[i]];
        g_node[i] = make_float2(z, powf(z, p) * d);
    }
}

// Compute per-edge energy from already-gathered node data (no memory ops).
__device__ __forceinline__ float edge_compute(float dd, float cc,
                                              float2 ni, float2 nj,
                                              float a0, float a1, float a2, float a3,
                                              float c0, float c1, float c2, float c3) {
    // x = (KE/2) * cutoff * z_i * z_j / (dist + 1e-8)
    float x = __fdividef(KE_HALF * cc * ni.x * nj.x, dd + 1e-8f);

    // rzd = dist * (z_i^p + z_j^p) * d   (d folded into node table .y)
    float rzd = dd * (ni.y + nj.y);

    float y = c0 * __expf(-a0 * rzd)
            + c1 * __expf(-a1 * rzd)
            + c2 * __expf(-a2 * rzd)
            + c3 * __expf(-a3 * rzd);

    // switch: w = 1 / (1 + exp(1/s1 - 1/sd)),  sd = d/1.5, s1 = 1 - d/1.5
    float sd = dd * (1.0f / 1.5f);
    float s1 = 1.0f - sd;
    sd = fmaxf(sd, 1e-8f);
    s1 = fmaxf(s1, 1e-8f);
    float t = __expf(__fdividef(1.0f, s1) - __fdividef(1.0f, sd));
    float w = __fdividef(1.0f, 1.0f + t);

    return w * x * y;
}

__global__ __launch_bounds__(256)
void edge_kernel(const float4* __restrict__ dist4,
                 const float4* __restrict__ cut4,
                 const int4* __restrict__ snd4,
                 const int4* __restrict__ rcv4,
                 float* __restrict__ out,
                 int n4, int n_tail_base, int n_edges) {
    int i = blockIdx.x * blockDim.x + threadIdx.x;

    float a0 = g_params[0], a1 = g_params[1], a2 = g_params[2], a3 = g_params[3];
    float c0 = g_params[4], c1 = g_params[5], c2 = g_params[6], c3 = g_params[7];

    if (i < n4) {
        // Streaming reads: evict-first (don't pollute L1/L2 hot set)
        float4 dv = __ldcs(&dist4[i]);
        float4 cv = __ldcs(&cut4[i]);
        int4   sv = __ldcs(&snd4[i]);
        int4   rv = __ldcs(&rcv4[i]);

        // Issue ALL 8 random gathers back-to-back (MLP = 8 per warp batch).
        float2 nj0 = g_node[sv.x];
        float2 nj1 = g_node[sv.y];
        float2 nj2 = g_node[sv.z];
        float2 nj3 = g_node[sv.w];
        float2 ni0 = g_node[rv.x];
        float2 ni1 = g_node[rv.y];
        float2 ni2 = g_node[rv.z];
        float2 ni3 = g_node[rv.w];

        // Compute (MUFU/FMA work overlaps other warps' memory latency)
        float e0 = edge_compute(dv.x, cv.x, ni0, nj0, a0,a1,a2,a3, c0,c1,c2,c3);
        float e1 = edge_compute(dv.y, cv.y, ni1, nj1, a0,a1,a2,a3, c0,c1,c2,c3);
        float e2 = edge_compute(dv.z, cv.z, ni2, nj2, a0,a1,a2,a3, c0,c1,c2,c3);
        float e3 = edge_compute(dv.w, cv.w, ni3, nj3, a0,a1,a2,a3, c0,c1,c2,c3);

        // Scatter (RED, no return)
        atomicAdd(&out[rv.x], e0);
        atomicAdd(&out[rv.y], e1);
        atomicAdd(&out[rv.z], e2);
        atomicAdd(&out[rv.w], e3);
    }

    // tail (n_edges not divisible by 4) — thread 0 scalar
    if (i == 0 && n_tail_base < n_edges) {
        const float* dist = (const float*)dist4;
        const float* cut  = (const float*)cut4;
        const int*   snd  = (const int*)snd4;
        const int*   rcv  = (const int*)rcv4;
        for (int e = n_tail_base; e < n_edges; e++) {
            float2 ni = g_node[rcv[e]];
            float2 nj = g_node[snd[e]];
            float en = edge_compute(dist[e], cut[e], ni, nj, a0,a1,a2,a3, c0,c1,c2,c3);
            atomicAdd(&out[rcv[e]], en);
        }
    }
}

extern "C" void kernel_launch(void* const* d_in, const int* in_sizes, int n_in,
                              void* d_out, int out_size) {
    const int*   node_species = (const int*)d_in[0];
    const float* distances    = (const float*)d_in[1];
    const float* cutoffs      = (const float*)d_in[2];
    const int*   senders      = (const int*)d_in[3];
    const int*   receivers    = (const int*)d_in[4];
    const int*   index_to_z   = (const int*)d_in[5];
    const float* a_raw        = (const float*)d_in[6];
    const float* c_raw        = (const float*)d_in[7];
    const float* p_raw        = (const float*)d_in[8];
    const float* d_raw        = (const float*)d_in[9];
    float* out = (float*)d_out;

    int n_nodes = in_sizes[0];
    int n_edges = in_sizes[1];

    {
        int threads = 256;
        int blocks = (n_nodes + threads - 1) / threads;
        prep_kernel<<<blocks, threads>>>(node_species, index_to_z,
                                         a_raw, c_raw, p_raw, d_raw,
                                         out, n_nodes);
    }
    {
        int n4 = n_edges >> 2;
        int threads = 256;
        int blocks = (n4 + threads - 1) / threads;
        if (blocks == 0) blocks = 1;
        edge_kernel<<<blocks, threads>>>((const float4*)distances,
                                         (const float4*)cutoffs,
                                         (const int4*)senders,
                                         (const int4*)receivers,
                                         out, n4, n4 << 2, n_edges);
    }
}

// round 5
// speedup vs baseline: 1.0634x; 1.0634x over previous
#include <cuda_runtime.h>
#include <cuda_bf16.h>

#define N_NODES_MAX 1000000
#define KE_HALF 7.199822675975274f   // 14.399645351950548 / 2

// Per-node z value (index_to_z[species[i]], values 1..100 fit in u8). 1 MB -> partly L1-resident.
__device__ unsigned char g_z[N_NODES_MAX];
// a0*d..a3*d, c0..c3 (normalized), p
__device__ float g_params[9];

__device__ __forceinline__ float softplus_f(float x) {
    return log1pf(expf(x));
}

__global__ void prep_kernel(const int* __restrict__ species,
                            const int* __restrict__ index_to_z,
                            const float* __restrict__ a_raw,
                            const float* __restrict__ c_raw,
                            const float* __restrict__ p_raw,
                            const float* __restrict__ d_raw,
                            float* __restrict__ out,
                            int n_nodes) {
    int i = blockIdx.x * blockDim.x + threadIdx.x;

    if (i < 9) {
        float d = softplus_f(d_raw[0]);
        if (i < 4) {
            g_params[i] = softplus_f(a_raw[i]) * d;     // fold d into a_k
        } else if (i < 8) {
            float c0 = softplus_f(c_raw[0]);
            float c1 = softplus_f(c_raw[1]);
            float c2 = softplus_f(c_raw[2]);
            float c3 = softplus_f(c_raw[3]);
            float inv_s = 1.0f / (c0 + c1 + c2 + c3);
            g_params[i] = softplus_f(c_raw[i - 4]) * inv_s;
        } else {
            g_params[8] = softplus_f(p_raw[0]);         // p
        }
    }

    if (i < n_nodes) {
        out[i] = 0.0f;  // zero-init accumulator (harness poisons d_out)
        g_z[i] = (unsigned char)index_to_z[species[i]];
    }
}

// Full per-edge energy from z values (all math, no memory).
__device__ __forceinline__ float edge_compute(float dd, float cc,
                                              float zi, float zj,
                                              float a0, float a1, float a2, float a3,
                                              float c0, float c1, float c2, float c3,
                                              float p) {
    // z^p via exp(p*log z); z >= 1 so log is safe, z=1 -> exactly 1
    float zpi = __expf(p * __logf(zi));
    float zpj = __expf(p * __logf(zj));

    // x = (KE/2) * cutoff * z_i * z_j / (dist + 1e-8)
    float x = __fdividef(KE_HALF * cc * zi * zj, dd + 1e-8f);

    // rzd*d folded: t = dist * (zi^p + zj^p); a_k already scaled by d
    float t = dd * (zpi + zpj);

    float y = c0 * __expf(-a0 * t)
            + c1 * __expf(-a1 * t)
            + c2 * __expf(-a2 * t)
            + c3 * __expf(-a3 * t);

    // switch: w = 1 / (1 + exp(1/s1 - 1/sd)),  sd = d/1.5, s1 = 1 - d/1.5
    float sd = dd * (1.0f / 1.5f);
    float s1 = 1.0f - sd;
    sd = fmaxf(sd, 1e-8f);
    s1 = fmaxf(s1, 1e-8f);
    float e = __expf(__fdividef(1.0f, s1) - __fdividef(1.0f, sd));
    float w = __fdividef(1.0f, 1.0f + e);

    return w * x * y;
}

__global__ __launch_bounds__(256)
void edge_kernel(const float4* __restrict__ dist4,
                 const float4* __restrict__ cut4,
                 const int4* __restrict__ snd4,
                 const int4* __restrict__ rcv4,
                 float* __restrict__ out,
                 int n4, int n_tail_base, int n_edges) {
    int i = blockIdx.x * blockDim.x + threadIdx.x;

    float a0 = g_params[0], a1 = g_params[1], a2 = g_params[2], a3 = g_params[3];
    float c0 = g_params[4], c1 = g_params[5], c2 = g_params[6], c3 = g_params[7];
    float p  = g_params[8];

    if (i < n4) {
        // Streaming reads: evict-first — keeps the 1 MB z-table resident in L1
        float4 dv = __ldcs(&dist4[i]);
        float4 cv = __ldcs(&cut4[i]);
        int4   sv = __ldcs(&snd4[i]);
        int4   rv = __ldcs(&rcv4[i]);

        // 8 random u8 gathers, back-to-back (1 MB table -> ~20-25% L1 hit)
        float zj0 = (float)g_z[sv.x];
        float zj1 = (float)g_z[sv.y];
        float zj2 = (float)g_z[sv.z];
        float zj3 = (float)g_z[sv.w];
        float zi0 = (float)g_z[rv.x];
        float zi1 = (float)g_z[rv.y];
        float zi2 = (float)g_z[rv.z];
        float zi3 = (float)g_z[rv.w];

        float e0 = edge_compute(dv.x, cv.x, zi0, zj0, a0,a1,a2,a3, c0,c1,c2,c3, p);
        float e1 = edge_compute(dv.y, cv.y, zi1, zj1, a0,a1,a2,a3, c0,c1,c2,c3, p);
        float e2 = edge_compute(dv.z, cv.z, zi2, zj2, a0,a1,a2,a3, c0,c1,c2,c3, p);
        float e3 = edge_compute(dv.w, cv.w, zi3, zj3, a0,a1,a2,a3, c0,c1,c2,c3, p);

        atomicAdd(&out[rv.x], e0);
        atomicAdd(&out[rv.y], e1);
        atomicAdd(&out[rv.z], e2);
        atomicAdd(&out[rv.w], e3);
    }

    // tail (n_edges not divisible by 4) — thread 0 scalar
    if (i == 0 && n_tail_base < n_edges) {
        const float* dist = (const float*)dist4;
        const float* cut  = (const float*)cut4;
        const int*   snd  = (const int*)snd4;
        const int*   rcv  = (const int*)rcv4;
        for (int e = n_tail_base; e < n_edges; e++) {
            float zi = (float)g_z[rcv[e]];
            float zj = (float)g_z[snd[e]];
            float en = edge_compute(dist[e], cut[e], zi, zj, a0,a1,a2,a3, c0,c1,c2,c3, p);
            atomicAdd(&out[rcv[e]], en);
        }
    }
}

extern "C" void kernel_launch(void* const* d_in, const int* in_sizes, int n_in,
                              void* d_out, int out_size) {
    const int*   node_species = (const int*)d_in[0];
    const float* distances    = (const float*)d_in[1];
    const float* cutoffs      = (const float*)d_in[2];
    const int*   senders      = (const int*)d_in[3];
    const int*   receivers    = (const int*)d_in[4];
    const int*   index_to_z   = (const int*)d_in[5];
    const float* a_raw        = (const float*)d_in[6];
    const float* c_raw        = (const float*)d_in[7];
    const float* p_raw        = (const float*)d_in[8];
    const float* d_raw        = (const float*)d_in[9];
    float* out = (float*)d_out;

    int n_nodes = in_sizes[0];
    int n_edges = in_sizes[1];

    {
        int threads = 256;
        int blocks = (n_nodes + threads - 1) / threads;
        prep_kernel<<<blocks, threads>>>(node_species, index_to_z,
                                         a_raw, c_raw, p_raw, d_raw,
                                         out, n_nodes);
    }
    {
        int n4 = n_edges >> 2;
        int threads = 256;
        int blocks = (n4 + threads - 1) / threads;
        if (blocks == 0) blocks = 1;
        edge_kernel<<<blocks, threads>>>((const float4*)distances,
                                         (const float4*)cutoffs,
                                         (const int4*)senders,
                                         (const int4*)receivers,
                                         out, n4, n4 << 2, n_edges);
    }
}